// round 1
// baseline (speedup 1.0000x reference)
#include <cuda_runtime.h>
#include <math.h>

// Problem constants
#define T_STEPS 100
#define BATCH   64
#define ISZ     256
#define HSZ     512
#define G4      2048   // 4H
#define G3      1536   // 3H

// Output layout (tuple concat): outputs[T,B,H], cx[B,H], ev_ih[B,3H,I], ev_hh[B,3H,H], ev_b[B,3H,1]
#define OUT_OUT  0
#define OUT_CX   (T_STEPS*BATCH*HSZ)               // 3,276,800
#define OUT_EVIH (OUT_CX + BATCH*HSZ)              // 3,309,568
#define OUT_EVHH (OUT_EVIH + BATCH*G3*ISZ)         // 28,475,392
#define OUT_EVB  (OUT_EVHH + BATCH*G3*HSZ)         // 78,807,040

// Device scratch (allocation-free: static __device__ globals)
__device__ float g_bias[G4];
__device__ float g_Gin[T_STEPS*BATCH*G4];          // input-side gates + bias
__device__ float g_hh[T_STEPS*BATCH*HSZ];          // h_{t-1} history (hx at step t)
__device__ float g_d[T_STEPS*BATCH*G3];            // d_t, later scaled to a_t
__device__ float g_f[T_STEPS*BATCH*HSZ];           // forget gates
__device__ float g_hbuf[2][BATCH*HSZ];             // double-buffered h
__device__ float g_ccur[BATCH*HSZ];
__device__ unsigned g_bar_cnt;
__device__ volatile unsigned g_bar_gen;

// ---------------------------------------------------------------------------
// prep: combined bias + initial h/c
__global__ void prep_kernel(const float* __restrict__ bih, const float* __restrict__ bhh,
                            const float* __restrict__ h0,  const float* __restrict__ c0) {
    int gid = blockIdx.x * blockDim.x + threadIdx.x;
    if (gid < G4) g_bias[gid] = bih[gid] + bhh[gid];
    if (gid < BATCH*HSZ) {
        g_hbuf[0][gid] = h0[gid];
        g_ccur[gid]    = c0[gid];
    }
}

// ---------------------------------------------------------------------------
// Gin[r][j] = sum_i X[r][i] * W_ih[j][i] + bias[j],  r in [T*B], j in [4H]
// Tiled 64x64, Kc=32, 256 threads, 4x4 register tiles.
__global__ __launch_bounds__(256) void gin_kernel(const float* __restrict__ X,
                                                  const float* __restrict__ Wih) {
    __shared__ float As[64][33];   // [row][k]
    __shared__ float Bs[32][68];   // [k][col]
    const int j0 = blockIdx.x * 64;
    const int r0 = blockIdx.y * 64;
    const int tx = threadIdx.x & 15, ty = threadIdx.x >> 4;
    float acc[4][4] = {};
    for (int k0 = 0; k0 < ISZ; k0 += 32) {
        for (int idx = threadIdx.x; idx < 64*32; idx += 256) {
            int rr = idx >> 5, kk = idx & 31;
            As[rr][kk] = X[(r0+rr)*ISZ + k0 + kk];
        }
        // Bs[kk][jj] = W_ih[j0+jj][k0+kk]  (coalesced over kk)
        for (int idx = threadIdx.x; idx < 64*32; idx += 256) {
            int kk = idx & 31, jj = idx >> 5;
            Bs[kk][jj] = Wih[(j0+jj)*ISZ + k0 + kk];
        }
        __syncthreads();
        #pragma unroll
        for (int kk = 0; kk < 32; kk++) {
            float4 b4 = *(const float4*)&Bs[kk][tx*4];
            float a[4];
            #pragma unroll
            for (int r = 0; r < 4; r++) a[r] = As[ty*4+r][kk];
            #pragma unroll
            for (int r = 0; r < 4; r++) {
                acc[r][0] += a[r]*b4.x; acc[r][1] += a[r]*b4.y;
                acc[r][2] += a[r]*b4.z; acc[r][3] += a[r]*b4.w;
            }
        }
        __syncthreads();
    }
    float4 bias4 = *(const float4*)&g_bias[j0 + tx*4];
    #pragma unroll
    for (int r = 0; r < 4; r++) {
        float4 v = make_float4(acc[r][0]+bias4.x, acc[r][1]+bias4.y,
                               acc[r][2]+bias4.z, acc[r][3]+bias4.w);
        *(float4*)&g_Gin[(r0+ty*4+r)*G4 + j0 + tx*4] = v;
    }
}

// ---------------------------------------------------------------------------
// Persistent recurrence kernel: 128 CTAs x 256 threads, one grid barrier/step.
// CTA n owns h-slice [4n, 4n+4) across all 4 gates (16 gate-columns), all 64 b.
#define NB_REC 128
#define HS_STR 516

__device__ __forceinline__ void grid_sync(unsigned nb) {
    __syncthreads();
    if (threadIdx.x == 0) {
        unsigned g = g_bar_gen;
        __threadfence();
        if (atomicAdd(&g_bar_cnt, 1u) == nb - 1u) {
            g_bar_cnt = 0u;
            __threadfence();
            g_bar_gen = g + 1u;
        } else {
            while (g_bar_gen == g) { }
            __threadfence();
        }
    }
    __syncthreads();
}

__global__ __launch_bounds__(256) void recur_kernel(const float* __restrict__ Whh,
                                                    float* __restrict__ out) {
    extern __shared__ float sm[];
    float* hs  = sm;                       // [64][HS_STR]  h tile, b-major
    float* wsT = sm + 64*HS_STR;           // [16][HS_STR]  weight cols, k-contig
    float* gb  = wsT + 16*HS_STR;          // [64][17]      gate exchange
    const int tid = threadIdx.x;
    const int n   = blockIdx.x;
    const int jj  = tid & 15, bg = tid >> 4;           // GEMM mapping
    const int ab  = tid >> 2, ah = tid & 3;            // activation mapping
    const int ahg = n*4 + ah;                          // global h index

    // Fill wsT once: wsT[c][k] = W_hh[(gate*512 + n*4 + hloc)][k]
    for (int idx = tid; idx < 16*HSZ; idx += 256) {
        int c = idx >> 9, k = idx & 511;
        int jc = (c >> 2)*HSZ + n*4 + (c & 3);
        wsT[c*HS_STR + k] = Whh[jc*HSZ + k];
    }

    for (int t = 0; t < T_STEPS; t++) {
        const int cur = t & 1;
        // fill hs (all b, all k) from current h buffer
        for (int idx = tid; idx < 64*128; idx += 256) {
            int b = idx >> 7, q = idx & 127;
            float4 v = *(const float4*)&g_hbuf[cur][b*HSZ + q*4];
            *(float4*)&hs[b*HS_STR + q*4] = v;
        }
        __syncthreads();

        float acc0 = 0.f, acc1 = 0.f, acc2 = 0.f, acc3 = 0.f;
        const float* w = &wsT[jj*HS_STR];
        const float* h0p = &hs[(4*bg+0)*HS_STR];
        const float* h1p = &hs[(4*bg+1)*HS_STR];
        const float* h2p = &hs[(4*bg+2)*HS_STR];
        const float* h3p = &hs[(4*bg+3)*HS_STR];
        #pragma unroll 4
        for (int k = 0; k < HSZ; k += 4) {
            float4 w4 = *(const float4*)&w[k];
            float4 a0 = *(const float4*)&h0p[k];
            float4 a1 = *(const float4*)&h1p[k];
            float4 a2 = *(const float4*)&h2p[k];
            float4 a3 = *(const float4*)&h3p[k];
            acc0 += a0.x*w4.x + a0.y*w4.y + a0.z*w4.z + a0.w*w4.w;
            acc1 += a1.x*w4.x + a1.y*w4.y + a1.z*w4.z + a1.w*w4.w;
            acc2 += a2.x*w4.x + a2.y*w4.y + a2.z*w4.z + a2.w*w4.w;
            acc3 += a3.x*w4.x + a3.y*w4.y + a3.z*w4.z + a3.w*w4.w;
        }
        // add input-side gates, publish to gbuf
        {
            const int gate = jj >> 2, hloc = jj & 3;
            const int j = gate*HSZ + n*4 + hloc;
            const int ginbase = (t*BATCH)*G4 + j;
            gb[(4*bg+0)*17 + jj] = acc0 + g_Gin[ginbase + (4*bg+0)*G4];
            gb[(4*bg+1)*17 + jj] = acc1 + g_Gin[ginbase + (4*bg+1)*G4];
            gb[(4*bg+2)*17 + jj] = acc2 + g_Gin[ginbase + (4*bg+2)*G4];
            gb[(4*bg+3)*17 + jj] = acc3 + g_Gin[ginbase + (4*bg+3)*G4];
        }
        __syncthreads();

        // activation: thread -> (b=ab, h=ahg)
        {
            float xi = gb[ab*17 + 0  + ah];
            float xf = gb[ab*17 + 4  + ah];
            float xg = gb[ab*17 + 8  + ah];
            float xo = gb[ab*17 + 12 + ah];
            float ig = 1.f/(1.f + __expf(-xi));
            float fg = 1.f/(1.f + __expf(-xf));
            float gg = tanhf(xg);
            float og = 1.f/(1.f + __expf(-xo));
            float cold = g_ccur[ab*HSZ + ahg];
            float hold = g_hbuf[cur][ab*HSZ + ahg];
            float cnew = fg*cold + ig*gg;
            float hnew = og * tanhf(cnew);
            int rb = t*BATCH + ab;
            g_hh[rb*HSZ + ahg] = hold;
            g_f [rb*HSZ + ahg] = fg;
            int dbase = rb*G3 + ahg;
            g_d[dbase]        = gg*ig*(1.f - ig);
            g_d[dbase + HSZ]  = cold*fg*(1.f - fg);
            g_d[dbase + 2*HSZ]= ig*(1.f - gg*gg);
            out[t*BATCH*HSZ + ab*HSZ + ahg] = hnew;
            g_ccur[ab*HSZ + ahg] = cnew;
            g_hbuf[1-cur][ab*HSZ + ahg] = hnew;
            if (t == T_STEPS-1) out[OUT_CX + ab*HSZ + ahg] = cnew;
        }
        grid_sync(NB_REC);
    }
}

// ---------------------------------------------------------------------------
// Backward suffix-product scan: a_t = (prod_{s>t} f_s) * d_t, in place; ev_b = sum a_t
__global__ __launch_bounds__(256) void scan_kernel(float* __restrict__ out) {
    int gid = blockIdx.x * blockDim.x + threadIdx.x;   // 32768
    int b = gid >> 9, h = gid & 511;
    float F = 1.f, si = 0.f, sf = 0.f, sg = 0.f;
    for (int t = T_STEPS-1; t >= 0; t--) {
        int rb = t*BATCH + b;
        float fv = g_f[rb*HSZ + h];
        int dbase = rb*G3 + h;
        float di = g_d[dbase]         * F;
        float df = g_d[dbase + HSZ]   * F;
        float dg = g_d[dbase + 2*HSZ] * F;
        g_d[dbase]         = di;
        g_d[dbase + HSZ]   = df;
        g_d[dbase + 2*HSZ] = dg;
        si += di; sf += df; sg += dg;
        F *= fv;
    }
    out[OUT_EVB + b*G3 + h]         = si;
    out[OUT_EVB + b*G3 + HSZ + h]   = sf;
    out[OUT_EVB + b*G3 + 2*HSZ + h] = sg;
}

// ---------------------------------------------------------------------------
// Trace GEMM: ev[b][j][k] = sum_t a[t][b][j] * U[t][b][k].  K=100 (4 chunks of 25).
template<int UD>
__global__ __launch_bounds__(256) void trace_kernel(const float* __restrict__ Uext,
                                                    float* __restrict__ out) {
    __shared__ float As[25][68];
    __shared__ float Us[25][68];
    const float* U = (UD == HSZ) ? (const float*)g_hh : Uext;
    const int b = blockIdx.z, j0 = blockIdx.y*64, k0 = blockIdx.x*64;
    const int tx = threadIdx.x & 15, ty = threadIdx.x >> 4;
    float acc[4][4] = {};
    for (int t0 = 0; t0 < T_STEPS; t0 += 25) {
        for (int idx = threadIdx.x; idx < 25*64; idx += 256) {
            int tt = idx >> 6, c = idx & 63;
            int rb = (t0+tt)*BATCH + b;
            As[tt][c] = g_d[rb*G3 + j0 + c];
            Us[tt][c] = U[rb*UD + k0 + c];
        }
        __syncthreads();
        #pragma unroll
        for (int tt = 0; tt < 25; tt++) {
            float4 a4 = *(const float4*)&As[tt][ty*4];
            float4 u4 = *(const float4*)&Us[tt][tx*4];
            acc[0][0] += a4.x*u4.x; acc[0][1] += a4.x*u4.y; acc[0][2] += a4.x*u4.z; acc[0][3] += a4.x*u4.w;
            acc[1][0] += a4.y*u4.x; acc[1][1] += a4.y*u4.y; acc[1][2] += a4.y*u4.z; acc[1][3] += a4.y*u4.w;
            acc[2][0] += a4.z*u4.x; acc[2][1] += a4.z*u4.y; acc[2][2] += a4.z*u4.z; acc[2][3] += a4.z*u4.w;
            acc[3][0] += a4.w*u4.x; acc[3][1] += a4.w*u4.y; acc[3][2] += a4.w*u4.z; acc[3][3] += a4.w*u4.w;
        }
        __syncthreads();
    }
    size_t base = (size_t)b * G3 * UD;
    #pragma unroll
    for (int r = 0; r < 4; r++) {
        *(float4*)&out[base + (size_t)(j0+ty*4+r)*UD + k0 + tx*4] =
            make_float4(acc[r][0], acc[r][1], acc[r][2], acc[r][3]);
    }
}

// ---------------------------------------------------------------------------
extern "C" void kernel_launch(void* const* d_in, const int* in_sizes, int n_in,
                              void* d_out, int out_size) {
    const float* input = (const float*)d_in[0];   // [T,B,I]
    const float* h0    = (const float*)d_in[1];   // [B,H]
    const float* c0    = (const float*)d_in[2];   // [B,H]
    const float* Wih   = (const float*)d_in[3];   // [4H,I]
    const float* Whh   = (const float*)d_in[4];   // [4H,H]
    const float* bih   = (const float*)d_in[5];   // [4H]
    const float* bhh   = (const float*)d_in[6];   // [4H]
    float* out = (float*)d_out;

    const int rec_smem = (64*HS_STR + 16*HS_STR + 64*17) * (int)sizeof(float); // 169,472 B
    cudaFuncSetAttribute(recur_kernel, cudaFuncAttributeMaxDynamicSharedMemorySize, rec_smem);

    prep_kernel<<<128, 256>>>(bih, bhh, h0, c0);
    gin_kernel<<<dim3(G4/64, (T_STEPS*BATCH)/64), 256>>>(input, Wih);
    recur_kernel<<<NB_REC, 256, rec_smem>>>(Whh, out);
    scan_kernel<<<128, 256>>>(out);
    trace_kernel<ISZ><<<dim3(ISZ/64, G3/64, BATCH), 256>>>(input, out + OUT_EVIH);
    trace_kernel<HSZ><<<dim3(HSZ/64, G3/64, BATCH), 256>>>(input, out + OUT_EVHH);
}

// round 2
// speedup vs baseline: 1.3051x; 1.3051x over previous
#include <cuda_runtime.h>
#include <math.h>

// Problem constants
#define T_STEPS 100
#define BATCH   64
#define ISZ     256
#define HSZ     512
#define G4      2048   // 4H
#define G3      1536   // 3H

// Output layout: outputs[T,B,H], cx[B,H], ev_ih[B,3H,I], ev_hh[B,3H,H], ev_b[B,3H,1]
#define OUT_CX   (T_STEPS*BATCH*HSZ)
#define OUT_EVIH (OUT_CX + BATCH*HSZ)
#define OUT_EVHH (OUT_EVIH + BATCH*G3*ISZ)
#define OUT_EVB  (OUT_EVHH + BATCH*G3*HSZ)

typedef unsigned long long ull;

// Device scratch
__device__ float g_bias[G4];
__device__ float g_Gin[T_STEPS*BATCH*G4];
__device__ float g_hh[T_STEPS*BATCH*HSZ];          // h_{t-1} history, b-major rows
__device__ float g_d[T_STEPS*BATCH*G3];
__device__ float g_f[T_STEPS*BATCH*HSZ];
__device__ float g_hbuf[2][HSZ*BATCH];             // k-major: [h][b]
__device__ float g_ccur[BATCH*HSZ];
__device__ unsigned g_bar_cnt;
__device__ volatile unsigned g_bar_gen;

// ---- f32x2 packed helpers -------------------------------------------------
__device__ __forceinline__ ull ffma2(ull a, ull b, ull c) {
    ull d; asm("fma.rn.f32x2 %0, %1, %2, %3;" : "=l"(d) : "l"(a), "l"(b), "l"(c)); return d;
}
__device__ __forceinline__ ull fadd2(ull a, ull b) {
    ull d; asm("add.rn.f32x2 %0, %1, %2;" : "=l"(d) : "l"(a), "l"(b)); return d;
}
__device__ __forceinline__ ull fdup(float x) {
    ull d; asm("mov.b64 %0, {%1, %1};" : "=l"(d) : "f"(x)); return d;
}
__device__ __forceinline__ float2 unpk(ull v) {
    float2 r; asm("mov.b64 {%0, %1}, %2;" : "=f"(r.x), "=f"(r.y) : "l"(v)); return r;
}

// ---------------------------------------------------------------------------
__global__ void prep_kernel(const float* __restrict__ bih, const float* __restrict__ bhh,
                            const float* __restrict__ h0,  const float* __restrict__ c0) {
    int gid = blockIdx.x * blockDim.x + threadIdx.x;
    if (gid < G4) g_bias[gid] = bih[gid] + bhh[gid];
    if (gid < BATCH*HSZ) {
        int k = gid >> 6, b = gid & 63;
        g_hbuf[0][gid] = h0[b*HSZ + k];     // k-major
        g_ccur[gid]    = c0[gid];           // b-major
    }
}

// ---------------------------------------------------------------------------
// Gin[r][j] = sum_i X[r][i]*W_ih[j][i] + bias[j].  FFMA2 over j-pairs.
__global__ __launch_bounds__(256) void gin_kernel(const float* __restrict__ X,
                                                  const float* __restrict__ Wih) {
    __shared__ float As[64][33];
    __shared__ float Bs[32][68];
    const int j0 = blockIdx.x * 64;
    const int r0 = blockIdx.y * 64;
    const int tx = threadIdx.x & 15, ty = threadIdx.x >> 4;
    ull acc[4][2] = {};
    for (int k0 = 0; k0 < ISZ; k0 += 32) {
        for (int idx = threadIdx.x; idx < 64*32; idx += 256) {
            int rr = idx >> 5, kk = idx & 31;
            As[rr][kk] = X[(r0+rr)*ISZ + k0 + kk];
        }
        for (int idx = threadIdx.x; idx < 64*32; idx += 256) {
            int kk = idx & 31, jj = idx >> 5;
            Bs[kk][jj] = Wih[(j0+jj)*ISZ + k0 + kk];
        }
        __syncthreads();
        #pragma unroll
        for (int kk = 0; kk < 32; kk++) {
            ulonglong2 bv = *(const ulonglong2*)&Bs[kk][tx*4];
            #pragma unroll
            for (int r = 0; r < 4; r++) {
                ull a2 = fdup(As[ty*4+r][kk]);
                acc[r][0] = ffma2(a2, bv.x, acc[r][0]);
                acc[r][1] = ffma2(a2, bv.y, acc[r][1]);
            }
        }
        __syncthreads();
    }
    float4 bias4 = *(const float4*)&g_bias[j0 + tx*4];
    #pragma unroll
    for (int r = 0; r < 4; r++) {
        float2 lo = unpk(acc[r][0]), hi = unpk(acc[r][1]);
        float4 v = make_float4(lo.x+bias4.x, lo.y+bias4.y, hi.x+bias4.z, hi.y+bias4.w);
        *(float4*)&g_Gin[(r0+ty*4+r)*G4 + j0 + tx*4] = v;
    }
}

// ---------------------------------------------------------------------------
// Persistent recurrence: 128 CTAs x 512 threads.
// CTA n owns 16 gate-cols: j = (c>>2)*512 + n*4 + (c&3).
// Compute thread: lane=(tid&31): jj=lane&15, ksub=lane>>4; warp=(tid>>5): half=warp>>3, kseg=warp&7.
//   Holds W[jglob][k] for k = kseg*64 + kk*2 + ksub (kk 0..31) in registers.
//   Accumulates 16 batch-pairs (32*half + 2p, +1) with FFMA2.
#define NB_REC 128
#define RT     512
#define HS_STR 68

__device__ __forceinline__ void grid_sync(unsigned nb) {
    __syncthreads();
    if (threadIdx.x == 0) {
        unsigned g = g_bar_gen;
        __threadfence();
        if (atomicAdd(&g_bar_cnt, 1u) == nb - 1u) {
            g_bar_cnt = 0u;
            __threadfence();
            g_bar_gen = g + 1u;
        } else {
            while (g_bar_gen == g) { }
            __threadfence();
        }
    }
    __syncthreads();
}

__global__ __launch_bounds__(RT) void recur_kernel(const float* __restrict__ Whh,
                                                   float* __restrict__ out) {
    extern __shared__ float sm[];
    float* hs = sm;                              // [512][HS_STR]
    ull*   pt = (ull*)(sm + HSZ*HS_STR);         // [RT*17] f32x2 partials
    float* gb = (float*)(pt + RT*17);            // [64][17] gate exchange

    const int tid  = threadIdx.x;
    const int n    = blockIdx.x;
    const int lane = tid & 31;
    const int jj   = lane & 15, ksub = lane >> 4;
    const int wrp  = tid >> 5;
    const int half = wrp >> 3, kseg = wrp & 7;
    const int jglob = (jj >> 2)*HSZ + n*4 + (jj & 3);
    // reducer mapping
    const int jo = tid & 15, ho = (tid >> 4) & 1, po = tid >> 5;
    const int jo_glob = (jo >> 2)*HSZ + n*4 + (jo & 3);
    const int b0 = ho*32 + po*2;
    // activation mapping (tid < 256)
    const int ab = tid >> 2, ah = tid & 3, ahg = n*4 + ah;

    // persistent weight registers
    float wreg[32];
    {
        const float* wp = Whh + jglob*HSZ + kseg*64 + ksub;
        #pragma unroll
        for (int kk = 0; kk < 32; kk++) wreg[kk] = wp[kk*2];
    }
    const float* hthr = hs + (kseg*64 + ksub)*HS_STR + half*32;

    for (int t = 0; t < T_STEPS; t++) {
        const int cur = t & 1;
        // stage h (k-major) into smem: 8192 float4, coalesced
        {
            const float4* src = (const float4*)g_hbuf[cur];
            #pragma unroll
            for (int i = 0; i < 16; i++) {
                int idx = tid + i*RT;
                int k = idx >> 4, q = idx & 15;
                *(float4*)&hs[k*HS_STR + q*4] = src[idx];
            }
        }
        __syncthreads();

        // k-sliced GEMM with weights in registers
        ull acc[16];
        #pragma unroll
        for (int p = 0; p < 16; p++) acc[p] = 0ull;
        #pragma unroll
        for (int kk = 0; kk < 32; kk++) {
            const ulonglong2* hr = (const ulonglong2*)(hthr + kk*2*HS_STR);
            ull w2 = fdup(wreg[kk]);
            #pragma unroll
            for (int q = 0; q < 8; q++) {
                ulonglong2 hv = hr[q];
                acc[2*q]   = ffma2(hv.x, w2, acc[2*q]);
                acc[2*q+1] = ffma2(hv.y, w2, acc[2*q+1]);
            }
        }
        #pragma unroll
        for (int p = 0; p < 16; p++) pt[tid*17 + p] = acc[p];
        __syncthreads();

        // reduce 16 k-slices -> gate value (f32x2 over 2 batches), add Gin
        {
            ull s0 = 0ull, s1 = 0ull;
            #pragma unroll
            for (int ks = 0; ks < 8; ks++) {
                int t0 = (ho*8 + ks)*32 + jo;
                s0 = fadd2(s0, pt[t0*17 + po]);
                s1 = fadd2(s1, pt[(t0+16)*17 + po]);
            }
            float2 gv = unpk(fadd2(s0, s1));
            int row = t*BATCH + b0;
            gv.x += g_Gin[row*G4 + jo_glob];
            gv.y += g_Gin[(row+1)*G4 + jo_glob];
            gb[b0*17 + jo]     = gv.x;
            gb[(b0+1)*17 + jo] = gv.y;
        }
        __syncthreads();

        // activation: thread -> (b=ab, h=ahg)
        if (tid < 256) {
            float xi = gb[ab*17 + 0  + ah];
            float xf = gb[ab*17 + 4  + ah];
            float xg = gb[ab*17 + 8  + ah];
            float xo = gb[ab*17 + 12 + ah];
            float ig = 1.f/(1.f + __expf(-xi));
            float fg = 1.f/(1.f + __expf(-xf));
            float gg = tanhf(xg);
            float og = 1.f/(1.f + __expf(-xo));
            float cold = g_ccur[ab*HSZ + ahg];
            float hold = hs[ahg*HS_STR + ab];
            float cnew = fg*cold + ig*gg;
            float hnew = og * tanhf(cnew);
            int rb = t*BATCH + ab;
            g_hh[rb*HSZ + ahg] = hold;
            g_f [rb*HSZ + ahg] = fg;
            int dbase = rb*G3 + ahg;
            g_d[dbase]         = gg*ig*(1.f - ig);
            g_d[dbase + HSZ]   = cold*fg*(1.f - fg);
            g_d[dbase + 2*HSZ] = ig*(1.f - gg*gg);
            out[t*BATCH*HSZ + ab*HSZ + ahg] = hnew;
            g_ccur[ab*HSZ + ahg] = cnew;
            g_hbuf[1-cur][ahg*BATCH + ab] = hnew;     // k-major
            if (t == T_STEPS-1) out[OUT_CX + ab*HSZ + ahg] = cnew;
        }
        grid_sync(NB_REC);
    }
}

// ---------------------------------------------------------------------------
// Backward suffix-product scan: a_t = (prod_{s>t} f_s) * d_t; ev_b = sum a_t
__global__ __launch_bounds__(256) void scan_kernel(float* __restrict__ out) {
    int gid = blockIdx.x * blockDim.x + threadIdx.x;
    int b = gid >> 9, h = gid & 511;
    float F = 1.f, si = 0.f, sf = 0.f, sg = 0.f;
    #pragma unroll 4
    for (int t = T_STEPS-1; t >= 0; t--) {
        int rb = t*BATCH + b;
        float fv = g_f[rb*HSZ + h];
        int dbase = rb*G3 + h;
        float di = g_d[dbase]         * F;
        float df = g_d[dbase + HSZ]   * F;
        float dg = g_d[dbase + 2*HSZ] * F;
        g_d[dbase]         = di;
        g_d[dbase + HSZ]   = df;
        g_d[dbase + 2*HSZ] = dg;
        si += di; sf += df; sg += dg;
        F *= fv;
    }
    out[OUT_EVB + b*G3 + h]         = si;
    out[OUT_EVB + b*G3 + HSZ + h]   = sf;
    out[OUT_EVB + b*G3 + 2*HSZ + h] = sg;
}

// ---------------------------------------------------------------------------
// Trace GEMM: ev[b][j][k] = sum_t a[t][b][j] * U[t][b][k].  FFMA2 over j-pairs.
template<int UD>
__global__ __launch_bounds__(256) void trace_kernel(const float* __restrict__ Uext,
                                                    float* __restrict__ out) {
    __shared__ float As[25][68];
    __shared__ float Us[25][68];
    const float* U = (UD == HSZ) ? (const float*)g_hh : Uext;
    const int b = blockIdx.z, j0 = blockIdx.y*64, k0 = blockIdx.x*64;
    const int tx = threadIdx.x & 15, ty = threadIdx.x >> 4;
    ull acc01[4] = {}, acc23[4] = {};
    for (int t0 = 0; t0 < T_STEPS; t0 += 25) {
        for (int idx = threadIdx.x; idx < 25*64; idx += 256) {
            int tt = idx >> 6, c = idx & 63;
            int rb = (t0+tt)*BATCH + b;
            As[tt][c] = g_d[rb*G3 + j0 + c];
            Us[tt][c] = U[rb*UD + k0 + c];
        }
        __syncthreads();
        #pragma unroll
        for (int tt = 0; tt < 25; tt++) {
            ulonglong2 av = *(const ulonglong2*)&As[tt][ty*4];   // (a0,a1),(a2,a3)
            float4 u4 = *(const float4*)&Us[tt][tx*4];
            ull u0 = fdup(u4.x), u1 = fdup(u4.y), u2 = fdup(u4.z), u3 = fdup(u4.w);
            acc01[0] = ffma2(av.x, u0, acc01[0]);
            acc01[1] = ffma2(av.x, u1, acc01[1]);
            acc01[2] = ffma2(av.x, u2, acc01[2]);
            acc01[3] = ffma2(av.x, u3, acc01[3]);
            acc23[0] = ffma2(av.y, u0, acc23[0]);
            acc23[1] = ffma2(av.y, u1, acc23[1]);
            acc23[2] = ffma2(av.y, u2, acc23[2]);
            acc23[3] = ffma2(av.y, u3, acc23[3]);
        }
        __syncthreads();
    }
    size_t base = (size_t)b * G3 * UD;
    float2 r0c0 = unpk(acc01[0]), r0c1 = unpk(acc01[1]), r0c2 = unpk(acc01[2]), r0c3 = unpk(acc01[3]);
    float2 r2c0 = unpk(acc23[0]), r2c1 = unpk(acc23[1]), r2c2 = unpk(acc23[2]), r2c3 = unpk(acc23[3]);
    *(float4*)&out[base + (size_t)(j0+ty*4+0)*UD + k0 + tx*4] = make_float4(r0c0.x, r0c1.x, r0c2.x, r0c3.x);
    *(float4*)&out[base + (size_t)(j0+ty*4+1)*UD + k0 + tx*4] = make_float4(r0c0.y, r0c1.y, r0c2.y, r0c3.y);
    *(float4*)&out[base + (size_t)(j0+ty*4+2)*UD + k0 + tx*4] = make_float4(r2c0.x, r2c1.x, r2c2.x, r2c3.x);
    *(float4*)&out[base + (size_t)(j0+ty*4+3)*UD + k0 + tx*4] = make_float4(r2c0.y, r2c1.y, r2c2.y, r2c3.y);
}

// ---------------------------------------------------------------------------
extern "C" void kernel_launch(void* const* d_in, const int* in_sizes, int n_in,
                              void* d_out, int out_size) {
    const float* input = (const float*)d_in[0];
    const float* h0    = (const float*)d_in[1];
    const float* c0    = (const float*)d_in[2];
    const float* Wih   = (const float*)d_in[3];
    const float* Whh   = (const float*)d_in[4];
    const float* bih   = (const float*)d_in[5];
    const float* bhh   = (const float*)d_in[6];
    float* out = (float*)d_out;

    const int rec_smem = HSZ*HS_STR*4 + RT*17*8 + 64*17*4;   // 213,248 B
    cudaFuncSetAttribute(recur_kernel, cudaFuncAttributeMaxDynamicSharedMemorySize, rec_smem);

    prep_kernel<<<128, 256>>>(bih, bhh, h0, c0);
    gin_kernel<<<dim3(G4/64, (T_STEPS*BATCH)/64), 256>>>(input, Wih);
    recur_kernel<<<NB_REC, RT, rec_smem>>>(Whh, out);
    scan_kernel<<<128, 256>>>(out);
    trace_kernel<ISZ><<<dim3(ISZ/64, G3/64, BATCH), 256>>>(input, out + OUT_EVIH);
    trace_kernel<HSZ><<<dim3(HSZ/64, G3/64, BATCH), 256>>>(input, out + OUT_EVHH);
}

// round 3
// speedup vs baseline: 1.3144x; 1.0072x over previous
#include <cuda_runtime.h>
#include <math.h>

// Problem constants
#define T_STEPS 100
#define BATCH   64
#define ISZ     256
#define HSZ     512
#define G4      2048   // 4H
#define G3      1536   // 3H
#define NCHUNK  4
#define CLEN    25

// Output layout: outputs[T,B,H], cx[B,H], ev_ih[B,3H,I], ev_hh[B,3H,H], ev_b[B,3H,1]
#define OUT_CX   (T_STEPS*BATCH*HSZ)
#define OUT_EVIH (OUT_CX + BATCH*HSZ)
#define OUT_EVHH (OUT_EVIH + BATCH*G3*ISZ)
#define OUT_EVB  (OUT_EVHH + BATCH*G3*HSZ)

typedef unsigned long long ull;

// Device scratch
__device__ float g_bias[G4];
__device__ float g_Gin[T_STEPS*BATCH*G4];
__device__ float g_hh[T_STEPS*BATCH*HSZ];
__device__ float g_d[T_STEPS*BATCH*G3];
__device__ float g_f[T_STEPS*BATCH*HSZ];
__device__ float g_hbuf[2][HSZ*BATCH];             // k-major: [h][b]
__device__ float g_ccur[BATCH*HSZ];
__device__ float g_Fc[NCHUNK][BATCH*HSZ];          // per-chunk forget products
__device__ float g_ps[NCHUNK][BATCH*G3];           // per-chunk ev_b partial sums
__device__ unsigned g_bar_cnt;
__device__ volatile unsigned g_bar_gen;

// ---- f32x2 packed helpers -------------------------------------------------
__device__ __forceinline__ ull ffma2(ull a, ull b, ull c) {
    ull d; asm("fma.rn.f32x2 %0, %1, %2, %3;" : "=l"(d) : "l"(a), "l"(b), "l"(c)); return d;
}
__device__ __forceinline__ ull fadd2(ull a, ull b) {
    ull d; asm("add.rn.f32x2 %0, %1, %2;" : "=l"(d) : "l"(a), "l"(b)); return d;
}
__device__ __forceinline__ ull fdup(float x) {
    ull d; asm("mov.b64 %0, {%1, %1};" : "=l"(d) : "f"(x)); return d;
}
__device__ __forceinline__ float2 unpk(ull v) {
    float2 r; asm("mov.b64 {%0, %1}, %2;" : "=f"(r.x), "=f"(r.y) : "l"(v)); return r;
}

// ---------------------------------------------------------------------------
__global__ void prep_kernel(const float* __restrict__ bih, const float* __restrict__ bhh,
                            const float* __restrict__ h0,  const float* __restrict__ c0) {
    int gid = blockIdx.x * blockDim.x + threadIdx.x;
    if (gid < G4) g_bias[gid] = bih[gid] + bhh[gid];
    if (gid < BATCH*HSZ) {
        int k = gid >> 6, b = gid & 63;
        g_hbuf[0][gid] = h0[b*HSZ + k];     // k-major
        g_ccur[gid]    = c0[gid];           // b-major
    }
}

// ---------------------------------------------------------------------------
// Gin[r][j] = sum_i X[r][i]*W_ih[j][i] + bias[j].
// 128x128 tile, 8x8 per thread (j packed in f32x2), k-chunks of 32.
__global__ __launch_bounds__(256) void gin_kernel(const float* __restrict__ X,
                                                  const float* __restrict__ Wih) {
    __shared__ float As[32][136];   // [k][r]  (transposed X)
    __shared__ float Bs[32][136];   // [k][j]
    const int j0 = blockIdx.x * 128;
    const int r0 = blockIdx.y * 128;
    const int tx = threadIdx.x & 15, ty = threadIdx.x >> 4;
    ull acc[8][4] = {};             // [r][jpair]
    for (int k0 = 0; k0 < ISZ; k0 += 32) {
        for (int idx = threadIdx.x; idx < 128*8; idx += 256) {
            int rr = idx >> 3, kq = idx & 7;
            float4 v = *(const float4*)&X[(r0+rr)*ISZ + k0 + kq*4];
            As[kq*4+0][rr] = v.x; As[kq*4+1][rr] = v.y;
            As[kq*4+2][rr] = v.z; As[kq*4+3][rr] = v.w;
        }
        for (int idx = threadIdx.x; idx < 128*8; idx += 256) {
            int jj = idx >> 3, kq = idx & 7;
            float4 v = *(const float4*)&Wih[(j0+jj)*ISZ + k0 + kq*4];
            Bs[kq*4+0][jj] = v.x; Bs[kq*4+1][jj] = v.y;
            Bs[kq*4+2][jj] = v.z; Bs[kq*4+3][jj] = v.w;
        }
        __syncthreads();
        #pragma unroll
        for (int kk = 0; kk < 32; kk++) {
            float4 a0 = *(const float4*)&As[kk][ty*8];
            float4 a1 = *(const float4*)&As[kk][ty*8+4];
            ulonglong2 bv0 = *(const ulonglong2*)&Bs[kk][tx*8];
            ulonglong2 bv1 = *(const ulonglong2*)&Bs[kk][tx*8+4];
            ull ad[8];
            ad[0]=fdup(a0.x); ad[1]=fdup(a0.y); ad[2]=fdup(a0.z); ad[3]=fdup(a0.w);
            ad[4]=fdup(a1.x); ad[5]=fdup(a1.y); ad[6]=fdup(a1.z); ad[7]=fdup(a1.w);
            #pragma unroll
            for (int r = 0; r < 8; r++) {
                acc[r][0] = ffma2(ad[r], bv0.x, acc[r][0]);
                acc[r][1] = ffma2(ad[r], bv0.y, acc[r][1]);
                acc[r][2] = ffma2(ad[r], bv1.x, acc[r][2]);
                acc[r][3] = ffma2(ad[r], bv1.y, acc[r][3]);
            }
        }
        __syncthreads();
    }
    float4 b0 = *(const float4*)&g_bias[j0 + tx*8];
    float4 b1 = *(const float4*)&g_bias[j0 + tx*8 + 4];
    #pragma unroll
    for (int r = 0; r < 8; r++) {
        float2 p0 = unpk(acc[r][0]), p1 = unpk(acc[r][1]);
        float2 p2 = unpk(acc[r][2]), p3 = unpk(acc[r][3]);
        float* dst = &g_Gin[(r0+ty*8+r)*G4 + j0 + tx*8];
        *(float4*)dst       = make_float4(p0.x+b0.x, p0.y+b0.y, p1.x+b0.z, p1.y+b0.w);
        *(float4*)(dst + 4) = make_float4(p2.x+b1.x, p2.y+b1.y, p3.x+b1.z, p3.y+b1.w);
    }
}

// ---------------------------------------------------------------------------
// Persistent recurrence: 128 CTAs x 512 threads.
#define NB_REC 128
#define RT     512
#define HS_STR 68

__device__ __forceinline__ void grid_sync(unsigned nb) {
    __syncthreads();
    if (threadIdx.x == 0) {
        unsigned g = g_bar_gen;
        __threadfence();
        if (atomicAdd(&g_bar_cnt, 1u) == nb - 1u) {
            g_bar_cnt = 0u;
            __threadfence();
            g_bar_gen = g + 1u;
        } else {
            while (g_bar_gen == g) { }
            __threadfence();
        }
    }
    __syncthreads();
}

__global__ __launch_bounds__(RT) void recur_kernel(const float* __restrict__ Whh,
                                                   float* __restrict__ out) {
    extern __shared__ float sm[];
    float* hs = sm;                              // [512][HS_STR]
    ull*   pt = (ull*)(sm + HSZ*HS_STR);         // [RT*17] f32x2 partials
    float* gb = (float*)(pt + RT*17);            // [64][17] gate exchange

    const int tid  = threadIdx.x;
    const int n    = blockIdx.x;
    const int lane = tid & 31;
    const int jj   = lane & 15, ksub = lane >> 4;
    const int wrp  = tid >> 5;
    const int half = wrp >> 3, kseg = wrp & 7;
    const int jglob = (jj >> 2)*HSZ + n*4 + (jj & 3);
    const int jo = tid & 15, ho = (tid >> 4) & 1, po = tid >> 5;
    const int jo_glob = (jo >> 2)*HSZ + n*4 + (jo & 3);
    const int b0 = ho*32 + po*2;
    const int ab = tid >> 2, ah = tid & 3, ahg = n*4 + ah;

    float wreg[32];
    {
        const float* wp = Whh + jglob*HSZ + kseg*64 + ksub;
        #pragma unroll
        for (int kk = 0; kk < 32; kk++) wreg[kk] = wp[kk*2];
    }
    const float* hthr = hs + (kseg*64 + ksub)*HS_STR + half*32;
    float Facc = 1.f;

    for (int t = 0; t < T_STEPS; t++) {
        const int cur = t & 1;
        {
            const float4* src = (const float4*)g_hbuf[cur];
            #pragma unroll
            for (int i = 0; i < 16; i++) {
                int idx = tid + i*RT;
                int k = idx >> 4, q = idx & 15;
                *(float4*)&hs[k*HS_STR + q*4] = src[idx];
            }
        }
        __syncthreads();

        ull acc[16];
        #pragma unroll
        for (int p = 0; p < 16; p++) acc[p] = 0ull;
        #pragma unroll
        for (int kk = 0; kk < 32; kk++) {
            const ulonglong2* hr = (const ulonglong2*)(hthr + kk*2*HS_STR);
            ull w2 = fdup(wreg[kk]);
            #pragma unroll
            for (int q = 0; q < 8; q++) {
                ulonglong2 hv = hr[q];
                acc[2*q]   = ffma2(hv.x, w2, acc[2*q]);
                acc[2*q+1] = ffma2(hv.y, w2, acc[2*q+1]);
            }
        }
        #pragma unroll
        for (int p = 0; p < 16; p++) pt[tid*17 + p] = acc[p];
        __syncthreads();

        {
            ull s0 = 0ull, s1 = 0ull;
            #pragma unroll
            for (int ks = 0; ks < 8; ks++) {
                int t0 = (ho*8 + ks)*32 + jo;
                s0 = fadd2(s0, pt[t0*17 + po]);
                s1 = fadd2(s1, pt[(t0+16)*17 + po]);
            }
            float2 gv = unpk(fadd2(s0, s1));
            int row = t*BATCH + b0;
            gv.x += g_Gin[row*G4 + jo_glob];
            gv.y += g_Gin[(row+1)*G4 + jo_glob];
            gb[b0*17 + jo]     = gv.x;
            gb[(b0+1)*17 + jo] = gv.y;
        }
        __syncthreads();

        if (tid < 256) {
            float xi = gb[ab*17 + 0  + ah];
            float xf = gb[ab*17 + 4  + ah];
            float xg = gb[ab*17 + 8  + ah];
            float xo = gb[ab*17 + 12 + ah];
            float ig = 1.f/(1.f + __expf(-xi));
            float fg = 1.f/(1.f + __expf(-xf));
            float gg = tanhf(xg);
            float og = 1.f/(1.f + __expf(-xo));
            float cold = g_ccur[ab*HSZ + ahg];
            float hold = hs[ahg*HS_STR + ab];
            float cnew = fg*cold + ig*gg;
            float hnew = og * tanhf(cnew);
            int rb = t*BATCH + ab;
            g_hh[rb*HSZ + ahg] = hold;
            g_f [rb*HSZ + ahg] = fg;
            int dbase = rb*G3 + ahg;
            g_d[dbase]         = gg*ig*(1.f - ig);
            g_d[dbase + HSZ]   = cold*fg*(1.f - fg);
            g_d[dbase + 2*HSZ] = ig*(1.f - gg*gg);
            out[t*BATCH*HSZ + ab*HSZ + ahg] = hnew;
            g_ccur[ab*HSZ + ahg] = cnew;
            g_hbuf[1-cur][ahg*BATCH + ab] = hnew;
            Facc *= fg;
            if ((t % CLEN) == CLEN-1) {
                g_Fc[t/CLEN][ab*HSZ + ahg] = Facc;
                Facc = 1.f;
            }
            if (t == T_STEPS-1) out[OUT_CX + ab*HSZ + ahg] = cnew;
        }
        grid_sync(NB_REC);
    }
}

// ---------------------------------------------------------------------------
// scanB: per time-chunk suffix scan. a_t = d_t * (local suffix product * Q_chunk)
__global__ __launch_bounds__(256) void scanB_kernel() {
    int gid = blockIdx.x * blockDim.x + threadIdx.x;    // 4*32768
    int c = gid >> 15, r = gid & 32767;
    int b = r >> 9, h = r & 511;
    float Q = 1.f;
    for (int c2 = c+1; c2 < NCHUNK; c2++) Q *= g_Fc[c2][b*HSZ + h];
    float F = Q, si = 0.f, sf = 0.f, sg = 0.f;
    #pragma unroll 5
    for (int t = c*CLEN + CLEN-1; t >= c*CLEN; t--) {
        int rb = t*BATCH + b;
        float fv = g_f[rb*HSZ + h];
        int dbase = rb*G3 + h;
        float di = g_d[dbase]         * F;
        float df = g_d[dbase + HSZ]   * F;
        float dg = g_d[dbase + 2*HSZ] * F;
        g_d[dbase]         = di;
        g_d[dbase + HSZ]   = df;
        g_d[dbase + 2*HSZ] = dg;
        si += di; sf += df; sg += dg;
        F *= fv;
    }
    g_ps[c][b*G3 + h]         = si;
    g_ps[c][b*G3 + HSZ + h]   = sf;
    g_ps[c][b*G3 + 2*HSZ + h] = sg;
}

// scanC: combine chunk partial sums -> ev_b
__global__ __launch_bounds__(256) void scanC_kernel(float* __restrict__ out) {
    int gid = blockIdx.x * blockDim.x + threadIdx.x;    // B*G3 = 98304
    float s = g_ps[0][gid] + g_ps[1][gid] + g_ps[2][gid] + g_ps[3][gid];
    out[OUT_EVB + gid] = s;
}

// ---------------------------------------------------------------------------
// Trace GEMM: ev[b][j][k] = sum_t a[t][b][j] * U[t][b][k].
// 128x128 tile, 8x8 per thread, j packed in f32x2, T staged in chunks of 25.
template<int UD>
__global__ __launch_bounds__(256) void trace_kernel(const float* __restrict__ Uext,
                                                    float* __restrict__ out) {
    __shared__ float As[25][136];
    __shared__ float Us[25][136];
    const float* U = (UD == HSZ) ? (const float*)g_hh : Uext;
    const int b = blockIdx.z, j0 = blockIdx.y*128, k0 = blockIdx.x*128;
    const int tx = threadIdx.x & 15, ty = threadIdx.x >> 4;
    ull acc[4][8] = {};    // [jpair][k]
    for (int t0 = 0; t0 < T_STEPS; t0 += 25) {
        for (int idx = threadIdx.x; idx < 25*32*2; idx += 256) {
            int which = idx >= 800;
            int i2 = which ? idx - 800 : idx;
            int tt = i2 >> 5, q = i2 & 31;
            int rb = (t0+tt)*BATCH + b;
            if (!which) *(float4*)&As[tt][q*4] = *(const float4*)&g_d[rb*G3 + j0 + q*4];
            else        *(float4*)&Us[tt][q*4] = *(const float4*)&U[rb*UD + k0 + q*4];
        }
        __syncthreads();
        #pragma unroll
        for (int tt = 0; tt < 25; tt++) {
            ulonglong2 a01 = *(const ulonglong2*)&As[tt][ty*8];
            ulonglong2 a23 = *(const ulonglong2*)&As[tt][ty*8+4];
            float4 u0 = *(const float4*)&Us[tt][tx*8];
            float4 u1 = *(const float4*)&Us[tt][tx*8+4];
            ull ud[8];
            ud[0]=fdup(u0.x); ud[1]=fdup(u0.y); ud[2]=fdup(u0.z); ud[3]=fdup(u0.w);
            ud[4]=fdup(u1.x); ud[5]=fdup(u1.y); ud[6]=fdup(u1.z); ud[7]=fdup(u1.w);
            #pragma unroll
            for (int k = 0; k < 8; k++) {
                acc[0][k] = ffma2(a01.x, ud[k], acc[0][k]);
                acc[1][k] = ffma2(a01.y, ud[k], acc[1][k]);
                acc[2][k] = ffma2(a23.x, ud[k], acc[2][k]);
                acc[3][k] = ffma2(a23.y, ud[k], acc[3][k]);
            }
        }
        __syncthreads();
    }
    size_t base = (size_t)b * G3 * UD;
    #pragma unroll
    for (int jp = 0; jp < 4; jp++) {
        float2 p[8];
        #pragma unroll
        for (int k = 0; k < 8; k++) p[k] = unpk(acc[jp][k]);
        float* d0 = &out[base + (size_t)(j0 + ty*8 + 2*jp)*UD + k0 + tx*8];
        float* d1 = &out[base + (size_t)(j0 + ty*8 + 2*jp + 1)*UD + k0 + tx*8];
        *(float4*)d0       = make_float4(p[0].x, p[1].x, p[2].x, p[3].x);
        *(float4*)(d0 + 4) = make_float4(p[4].x, p[5].x, p[6].x, p[7].x);
        *(float4*)d1       = make_float4(p[0].y, p[1].y, p[2].y, p[3].y);
        *(float4*)(d1 + 4) = make_float4(p[4].y, p[5].y, p[6].y, p[7].y);
    }
}

// ---------------------------------------------------------------------------
extern "C" void kernel_launch(void* const* d_in, const int* in_sizes, int n_in,
                              void* d_out, int out_size) {
    const float* input = (const float*)d_in[0];
    const float* h0    = (const float*)d_in[1];
    const float* c0    = (const float*)d_in[2];
    const float* Wih   = (const float*)d_in[3];
    const float* Whh   = (const float*)d_in[4];
    const float* bih   = (const float*)d_in[5];
    const float* bhh   = (const float*)d_in[6];
    float* out = (float*)d_out;

    const int rec_smem = HSZ*HS_STR*4 + RT*17*8 + 64*17*4;
    cudaFuncSetAttribute(recur_kernel, cudaFuncAttributeMaxDynamicSharedMemorySize, rec_smem);

    prep_kernel<<<128, 256>>>(bih, bhh, h0, c0);
    gin_kernel<<<dim3(G4/128, (T_STEPS*BATCH)/128), 256>>>(input, Wih);
    recur_kernel<<<NB_REC, RT, rec_smem>>>(Whh, out);
    scanB_kernel<<<NCHUNK*32768/256, 256>>>();
    scanC_kernel<<<BATCH*G3/256, 256>>>(out);
    trace_kernel<ISZ><<<dim3(ISZ/128, G3/128, BATCH), 256>>>(input, out + OUT_EVIH);
    trace_kernel<HSZ><<<dim3(HSZ/128, G3/128, BATCH), 256>>>(input, out + OUT_EVHH);
}

// round 4
// speedup vs baseline: 1.6479x; 1.2537x over previous
#include <cuda_runtime.h>
#include <math.h>

// Problem constants
#define T_STEPS 100
#define BATCH   64
#define ISZ     256
#define HSZ     512
#define G4      2048   // 4H
#define G3      1536   // 3H
#define NCHUNK  4
#define CLEN    25

// Output layout: outputs[T,B,H], cx[B,H], ev_ih[B,3H,I], ev_hh[B,3H,H], ev_b[B,3H,1]
#define OUT_CX   (T_STEPS*BATCH*HSZ)
#define OUT_EVIH (OUT_CX + BATCH*HSZ)
#define OUT_EVHH (OUT_EVIH + BATCH*G3*ISZ)
#define OUT_EVB  (OUT_EVHH + BATCH*G3*HSZ)

typedef unsigned long long ull;

// Device scratch
__device__ float g_bias[G4];
__device__ float g_Gin[T_STEPS*BATCH*G4];
__device__ float g_hh[T_STEPS*BATCH*HSZ];
__device__ float g_d[T_STEPS*BATCH*G3];
__device__ float g_f[T_STEPS*BATCH*HSZ];
__device__ float g_hbuf[2][HSZ*BATCH];             // k-major: [h][b]
__device__ float g_Fc[NCHUNK][BATCH*HSZ];
__device__ float g_ps[NCHUNK][BATCH*G3];
__device__ unsigned g_cnt2;

// ---- f32x2 packed helpers -------------------------------------------------
__device__ __forceinline__ ull ffma2(ull a, ull b, ull c) {
    ull d; asm("fma.rn.f32x2 %0, %1, %2, %3;" : "=l"(d) : "l"(a), "l"(b), "l"(c)); return d;
}
__device__ __forceinline__ ull fadd2(ull a, ull b) {
    ull d; asm("add.rn.f32x2 %0, %1, %2;" : "=l"(d) : "l"(a), "l"(b)); return d;
}
__device__ __forceinline__ ull fdup(float x) {
    ull d; asm("mov.b64 %0, {%1, %1};" : "=l"(d) : "f"(x)); return d;
}
__device__ __forceinline__ float2 unpk(ull v) {
    float2 r; asm("mov.b64 {%0, %1}, %2;" : "=f"(r.x), "=f"(r.y) : "l"(v)); return r;
}

// ---------------------------------------------------------------------------
__global__ void prep_kernel(const float* __restrict__ bih, const float* __restrict__ bhh,
                            const float* __restrict__ h0) {
    int gid = blockIdx.x * blockDim.x + threadIdx.x;
    if (gid == 0) g_cnt2 = 0u;
    if (gid < G4) g_bias[gid] = bih[gid] + bhh[gid];
    if (gid < BATCH*HSZ) {
        int k = gid >> 6, b = gid & 63;
        g_hbuf[0][gid] = h0[b*HSZ + k];     // k-major
    }
}

__global__ void dummy_kernel() {}

// ---------------------------------------------------------------------------
// Gin[r][j] = sum_i X[r][i]*W_ih[j][i] + bias[j].  128x128 tile, 8x8/thread.
__global__ __launch_bounds__(256) void gin_kernel(const float* __restrict__ X,
                                                  const float* __restrict__ Wih) {
    __shared__ float As[32][136];
    __shared__ float Bs[32][136];
    const int j0 = blockIdx.x * 128;
    const int r0 = blockIdx.y * 128;
    const int tx = threadIdx.x & 15, ty = threadIdx.x >> 4;
    ull acc[8][4] = {};
    for (int k0 = 0; k0 < ISZ; k0 += 32) {
        for (int idx = threadIdx.x; idx < 128*8; idx += 256) {
            int rr = idx >> 3, kq = idx & 7;
            float4 v = *(const float4*)&X[(r0+rr)*ISZ + k0 + kq*4];
            As[kq*4+0][rr] = v.x; As[kq*4+1][rr] = v.y;
            As[kq*4+2][rr] = v.z; As[kq*4+3][rr] = v.w;
        }
        for (int idx = threadIdx.x; idx < 128*8; idx += 256) {
            int jj = idx >> 3, kq = idx & 7;
            float4 v = *(const float4*)&Wih[(j0+jj)*ISZ + k0 + kq*4];
            Bs[kq*4+0][jj] = v.x; Bs[kq*4+1][jj] = v.y;
            Bs[kq*4+2][jj] = v.z; Bs[kq*4+3][jj] = v.w;
        }
        __syncthreads();
        #pragma unroll
        for (int kk = 0; kk < 32; kk++) {
            float4 a0 = *(const float4*)&As[kk][ty*8];
            float4 a1 = *(const float4*)&As[kk][ty*8+4];
            ulonglong2 bv0 = *(const ulonglong2*)&Bs[kk][tx*8];
            ulonglong2 bv1 = *(const ulonglong2*)&Bs[kk][tx*8+4];
            ull ad[8];
            ad[0]=fdup(a0.x); ad[1]=fdup(a0.y); ad[2]=fdup(a0.z); ad[3]=fdup(a0.w);
            ad[4]=fdup(a1.x); ad[5]=fdup(a1.y); ad[6]=fdup(a1.z); ad[7]=fdup(a1.w);
            #pragma unroll
            for (int r = 0; r < 8; r++) {
                acc[r][0] = ffma2(ad[r], bv0.x, acc[r][0]);
                acc[r][1] = ffma2(ad[r], bv0.y, acc[r][1]);
                acc[r][2] = ffma2(ad[r], bv1.x, acc[r][2]);
                acc[r][3] = ffma2(ad[r], bv1.y, acc[r][3]);
            }
        }
        __syncthreads();
    }
    float4 b0 = *(const float4*)&g_bias[j0 + tx*8];
    float4 b1 = *(const float4*)&g_bias[j0 + tx*8 + 4];
    #pragma unroll
    for (int r = 0; r < 8; r++) {
        float2 p0 = unpk(acc[r][0]), p1 = unpk(acc[r][1]);
        float2 p2 = unpk(acc[r][2]), p3 = unpk(acc[r][3]);
        float* dst = &g_Gin[(r0+ty*8+r)*G4 + j0 + tx*8];
        *(float4*)dst       = make_float4(p0.x+b0.x, p0.y+b0.y, p1.x+b0.z, p1.y+b0.w);
        *(float4*)(dst + 4) = make_float4(p2.x+b1.x, p2.y+b1.y, p3.x+b1.z, p3.y+b1.w);
    }
}

// ---------------------------------------------------------------------------
// Persistent recurrence v3: 128 CTAs x 512 threads.
// CTA n: batch-half hb=n&1 (32 b), cell-group cg=n>>1 (8 cells -> 32 gate-cols).
// Weights in smem (transposed), thread tile 4 cols x 8 batches, 16 k-slices.
#define NB_REC 128
#define RT     512
#define SROW   36            // padded row stride (floats) for ws/hs

// smem float offsets
#define OFF_WS 0
#define OFF_HS (512*SROW)                 // 18432
#define OFF_PT (2*512*SROW)               // 36864 (ull array, 16*513 ull)
#define OFF_GB (OFF_PT + 16*513*2)        // 53280
#define OFF_CS (OFF_GB + 32*33)           // 54336
#define REC_SMEM_FLOATS (OFF_CS + 256)    // 54592
#define REC_SMEM_BYTES  (REC_SMEM_FLOATS*4)

__device__ __forceinline__ void grid_sync2(int t) {
    __syncthreads();
    if (threadIdx.x == 0) {
        __threadfence();
        atomicAdd(&g_cnt2, 1u);
        unsigned target = (unsigned)(t + 1) * NB_REC;
        while (*(volatile unsigned*)&g_cnt2 < target) {}
        __threadfence();
    }
    __syncthreads();
}

__global__ __launch_bounds__(RT) void recur_kernel(const float* __restrict__ Whh,
                                                   const float* __restrict__ c0,
                                                   float* __restrict__ out) {
    extern __shared__ float sm[];
    float* ws = sm + OFF_WS;          // [512][SROW] ws[k][c]
    float* hs = sm + OFF_HS;          // [512][SROW] hs[k][b]
    ull*   pt = (ull*)(sm + OFF_PT);  // [16][513]
    float* gb = sm + OFF_GB;          // [32][33]
    float* cs = sm + OFF_CS;          // [256]

    const int tid = threadIdx.x;
    const int n   = blockIdx.x;
    const int hb  = n & 1, cg = n >> 1;
    // GEMM mapping
    const int ks = tid >> 5, lane = tid & 31;
    const int cq = lane >> 2, bq = lane & 3;
    // reduce mapping: r = tid -> i = r>>5 (c,bp inner), l = r&31 (cq,bq)
    const int rl = tid & 31, ri = tid >> 4;  // placeholder (recomputed below)
    (void)rl; (void)ri;
    const int r_l = tid & 31, r_i = tid >> 5;
    const int r_col = ((r_l >> 2) << 2) + (r_i >> 2);       // cq*4 + c
    const int r_bp  = ((r_l & 3) << 2) + (r_i & 3);         // bq*4 + bp
    const int r_jg  = ((r_col >> 3) * HSZ) + cg*8 + (r_col & 7);
    // activation mapping (tid < 256): b = tid>>3, cc = tid&7
    const int ab = tid >> 3, acc_ = tid & 7;
    const int ahg = cg*8 + acc_;             // global cell
    const int abg = hb*32 + ab;              // global batch

    // one-time: load weights transposed ws[k][c], c-state
    for (int idx = tid; idx < 32*512; idx += RT) {
        int c = idx >> 9, k = idx & 511;
        int jg = ((c >> 3) * HSZ) + cg*8 + (c & 7);
        ws[k*SROW + c] = Whh[jg*HSZ + k];
    }
    if (tid < 256) cs[tid] = c0[abg*HSZ + ahg];
    float Facc = 1.f;
    __syncthreads();

    for (int t = 0; t < T_STEPS; t++) {
        const int cur = t & 1;
        // stage h_{t-1}: our 32-batch half, all 512 k
        {
            const float* src = g_hbuf[cur];
            #pragma unroll
            for (int i = 0; i < 8; i++) {
                int idx = tid + i*RT;
                int k = idx >> 3, q = idx & 7;
                *(float4*)&hs[k*SROW + q*4] = *(const float4*)&src[k*64 + hb*32 + q*4];
            }
        }
        // prefetch Gin for reduce phase (L2 latency hidden behind GEMM)
        float gin0 = g_Gin[(t*BATCH + hb*32 + 2*r_bp    )*G4 + r_jg];
        float gin1 = g_Gin[(t*BATCH + hb*32 + 2*r_bp + 1)*G4 + r_jg];
        __syncthreads();

        // GEMM: thread = (ks, cq, bq); 4 cols x 8 batches over 32 k
        ull acc[16];
        #pragma unroll
        for (int p = 0; p < 16; p++) acc[p] = 0ull;
        {
            const float* hbase = hs + bq*8;
            const float* wbase = ws + cq*4;
            #pragma unroll
            for (int kk = 0; kk < 32; kk++) {
                int k = ks*32 + kk;
                ulonglong2 ha = *(const ulonglong2*)(hbase + k*SROW);
                ulonglong2 hc = *(const ulonglong2*)(hbase + k*SROW + 4);
                float4 wv = *(const float4*)(wbase + k*SROW);
                ull w0 = fdup(wv.x), w1 = fdup(wv.y), w2 = fdup(wv.z), w3 = fdup(wv.w);
                acc[0]  = ffma2(ha.x, w0, acc[0]);
                acc[1]  = ffma2(ha.y, w0, acc[1]);
                acc[2]  = ffma2(hc.x, w0, acc[2]);
                acc[3]  = ffma2(hc.y, w0, acc[3]);
                acc[4]  = ffma2(ha.x, w1, acc[4]);
                acc[5]  = ffma2(ha.y, w1, acc[5]);
                acc[6]  = ffma2(hc.x, w1, acc[6]);
                acc[7]  = ffma2(hc.y, w1, acc[7]);
                acc[8]  = ffma2(ha.x, w2, acc[8]);
                acc[9]  = ffma2(ha.y, w2, acc[9]);
                acc[10] = ffma2(hc.x, w2, acc[10]);
                acc[11] = ffma2(hc.y, w2, acc[11]);
                acc[12] = ffma2(ha.x, w3, acc[12]);
                acc[13] = ffma2(ha.y, w3, acc[13]);
                acc[14] = ffma2(hc.x, w3, acc[14]);
                acc[15] = ffma2(hc.y, w3, acc[15]);
            }
        }
        // store partials: oid = (c*4+bp)*32 + lane  (bank-clean)
        #pragma unroll
        for (int c = 0; c < 4; c++)
            #pragma unroll
            for (int bp = 0; bp < 4; bp++)
                pt[ks*513 + (c*4+bp)*32 + lane] = acc[c*4 + bp];
        __syncthreads();

        // reduce 16 k-slices; 4-way partial chains for ILP
        {
            ull s0 = 0ull, s1 = 0ull, s2 = 0ull, s3 = 0ull;
            #pragma unroll
            for (int s = 0; s < 4; s++) {
                s0 = fadd2(s0, pt[(s   )*513 + tid & 0x7FFFFFFF]);
                s1 = fadd2(s1, pt[(s+4 )*513 + (tid)]);
                s2 = fadd2(s2, pt[(s+8 )*513 + (tid)]);
                s3 = fadd2(s3, pt[(s+12)*513 + (tid)]);
            }
            // fix s0 indexing (avoid operator-precedence hazard above)
            s0 = 0ull;
            #pragma unroll
            for (int s = 0; s < 4; s++) s0 = fadd2(s0, pt[s*513 + tid]);
            float2 gv = unpk(fadd2(fadd2(s0, s1), fadd2(s2, s3)));
            gv.x += gin0;
            gv.y += gin1;
            gb[(2*r_bp    )*33 + r_col] = gv.x;
            gb[(2*r_bp + 1)*33 + r_col] = gv.y;
        }
        __syncthreads();

        // activation: thread -> (b=ab local, cell=acc_)
        if (tid < 256) {
            float xi = gb[ab*33 +      acc_];
            float xf = gb[ab*33 +  8 + acc_];
            float xg = gb[ab*33 + 16 + acc_];
            float xo = gb[ab*33 + 24 + acc_];
            float ig = 1.f/(1.f + __expf(-xi));
            float fg = 1.f/(1.f + __expf(-xf));
            float gg = tanhf(xg);
            float og = 1.f/(1.f + __expf(-xo));
            float cold = cs[tid];
            float hold = hs[ahg*SROW + ab];
            float cnew = fg*cold + ig*gg;
            float hnew = og * tanhf(cnew);
            int rb = t*BATCH + abg;
            g_hh[rb*HSZ + ahg] = hold;
            g_f [rb*HSZ + ahg] = fg;
            int dbase = rb*G3 + ahg;
            g_d[dbase]         = gg*ig*(1.f - ig);
            g_d[dbase + HSZ]   = cold*fg*(1.f - fg);
            g_d[dbase + 2*HSZ] = ig*(1.f - gg*gg);
            out[t*BATCH*HSZ + abg*HSZ + ahg] = hnew;
            cs[tid] = cnew;
            g_hbuf[1-cur][ahg*64 + abg] = hnew;
            Facc *= fg;
            if ((t % CLEN) == CLEN-1) {
                g_Fc[t/CLEN][abg*HSZ + ahg] = Facc;
                Facc = 1.f;
            }
            if (t == T_STEPS-1) out[OUT_CX + abg*HSZ + ahg] = cnew;
        }
        grid_sync2(t);
    }
}

// ---------------------------------------------------------------------------
__global__ __launch_bounds__(256) void scanB_kernel() {
    int gid = blockIdx.x * blockDim.x + threadIdx.x;
    int c = gid >> 15, r = gid & 32767;
    int b = r >> 9, h = r & 511;
    float Q = 1.f;
    for (int c2 = c+1; c2 < NCHUNK; c2++) Q *= g_Fc[c2][b*HSZ + h];
    float F = Q, si = 0.f, sf = 0.f, sg = 0.f;
    #pragma unroll 5
    for (int t = c*CLEN + CLEN-1; t >= c*CLEN; t--) {
        int rb = t*BATCH + b;
        float fv = g_f[rb*HSZ + h];
        int dbase = rb*G3 + h;
        float di = g_d[dbase]         * F;
        float df = g_d[dbase + HSZ]   * F;
        float dg = g_d[dbase + 2*HSZ] * F;
        g_d[dbase]         = di;
        g_d[dbase + HSZ]   = df;
        g_d[dbase + 2*HSZ] = dg;
        si += di; sf += df; sg += dg;
        F *= fv;
    }
    g_ps[c][b*G3 + h]         = si;
    g_ps[c][b*G3 + HSZ + h]   = sf;
    g_ps[c][b*G3 + 2*HSZ + h] = sg;
}

__global__ __launch_bounds__(256) void scanC_kernel(float* __restrict__ out) {
    int gid = blockIdx.x * blockDim.x + threadIdx.x;
    float s = g_ps[0][gid] + g_ps[1][gid] + g_ps[2][gid] + g_ps[3][gid];
    out[OUT_EVB + gid] = s;
}

// ---------------------------------------------------------------------------
// Trace GEMM: ev[b][j][k] = sum_t a[t][b][j] * U[t][b][k]. 128x128, 8x8/thread.
template<int UD>
__global__ __launch_bounds__(256) void trace_kernel(const float* __restrict__ Uext,
                                                    float* __restrict__ out) {
    __shared__ float As[25][136];
    __shared__ float Us[25][136];
    const float* U = (UD == HSZ) ? (const float*)g_hh : Uext;
    const int b = blockIdx.z, j0 = blockIdx.y*128, k0 = blockIdx.x*128;
    const int tx = threadIdx.x & 15, ty = threadIdx.x >> 4;
    ull acc[4][8] = {};
    for (int t0 = 0; t0 < T_STEPS; t0 += 25) {
        for (int idx = threadIdx.x; idx < 25*32*2; idx += 256) {
            int which = idx >= 800;
            int i2 = which ? idx - 800 : idx;
            int tt = i2 >> 5, q = i2 & 31;
            int rb = (t0+tt)*BATCH + b;
            if (!which) *(float4*)&As[tt][q*4] = *(const float4*)&g_d[rb*G3 + j0 + q*4];
            else        *(float4*)&Us[tt][q*4] = *(const float4*)&U[rb*UD + k0 + q*4];
        }
        __syncthreads();
        #pragma unroll
        for (int tt = 0; tt < 25; tt++) {
            ulonglong2 a01 = *(const ulonglong2*)&As[tt][ty*8];
            ulonglong2 a23 = *(const ulonglong2*)&As[tt][ty*8+4];
            float4 u0 = *(const float4*)&Us[tt][tx*8];
            float4 u1 = *(const float4*)&Us[tt][tx*8+4];
            ull ud[8];
            ud[0]=fdup(u0.x); ud[1]=fdup(u0.y); ud[2]=fdup(u0.z); ud[3]=fdup(u0.w);
            ud[4]=fdup(u1.x); ud[5]=fdup(u1.y); ud[6]=fdup(u1.z); ud[7]=fdup(u1.w);
            #pragma unroll
            for (int k = 0; k < 8; k++) {
                acc[0][k] = ffma2(a01.x, ud[k], acc[0][k]);
                acc[1][k] = ffma2(a01.y, ud[k], acc[1][k]);
                acc[2][k] = ffma2(a23.x, ud[k], acc[2][k]);
                acc[3][k] = ffma2(a23.y, ud[k], acc[3][k]);
            }
        }
        __syncthreads();
    }
    size_t base = (size_t)b * G3 * UD;
    #pragma unroll
    for (int jp = 0; jp < 4; jp++) {
        float2 p[8];
        #pragma unroll
        for (int k = 0; k < 8; k++) p[k] = unpk(acc[jp][k]);
        float* d0 = &out[base + (size_t)(j0 + ty*8 + 2*jp)*UD + k0 + tx*8];
        float* d1 = &out[base + (size_t)(j0 + ty*8 + 2*jp + 1)*UD + k0 + tx*8];
        *(float4*)d0       = make_float4(p[0].x, p[1].x, p[2].x, p[3].x);
        *(float4*)(d0 + 4) = make_float4(p[4].x, p[5].x, p[6].x, p[7].x);
        *(float4*)d1       = make_float4(p[0].y, p[1].y, p[2].y, p[3].y);
        *(float4*)(d1 + 4) = make_float4(p[4].y, p[5].y, p[6].y, p[7].y);
    }
}

// ---------------------------------------------------------------------------
extern "C" void kernel_launch(void* const* d_in, const int* in_sizes, int n_in,
                              void* d_out, int out_size) {
    const float* input = (const float*)d_in[0];
    const float* h0    = (const float*)d_in[1];
    const float* c0    = (const float*)d_in[2];
    const float* Wih   = (const float*)d_in[3];
    const float* Whh   = (const float*)d_in[4];
    const float* bih   = (const float*)d_in[5];
    const float* bhh   = (const float*)d_in[6];
    float* out = (float*)d_out;

    cudaFuncSetAttribute(recur_kernel, cudaFuncAttributeMaxDynamicSharedMemorySize, REC_SMEM_BYTES);

    prep_kernel<<<128, 256>>>(bih, bhh, h0);                                     // 0
    gin_kernel<<<dim3(G4/128, (T_STEPS*BATCH)/128), 256>>>(input, Wih);          // 1
    dummy_kernel<<<1, 32>>>();                                                   // 2
    recur_kernel<<<NB_REC, RT, REC_SMEM_BYTES>>>(Whh, c0, out);                  // 3 (profiled)
    scanB_kernel<<<NCHUNK*32768/256, 256>>>();                                   // 4
    scanC_kernel<<<BATCH*G3/256, 256>>>(out);                                    // 5
    trace_kernel<ISZ><<<dim3(ISZ/128, G3/128, BATCH), 256>>>(input, out + OUT_EVIH);
    trace_kernel<HSZ><<<dim3(HSZ/128, G3/128, BATCH), 256>>>(input, out + OUT_EVHH);
}